// round 9
// baseline (speedup 1.0000x reference)
#include <cuda_runtime.h>
#include <math.h>
#include <stdint.h>

#define POS_DIM 288
#define NFREQ   12
#define CP      288      // padded pitch for weights rows (16B-aligned)
#define BM      64       // m-tile (o): 5 blocks over O=270
#define BN      128
#define BK      32
#define AP      36       // K-major smem pitch: ldmatrix + scalar reads conflict-free
#define SP      136      // staging pitch: 136 % 32 == 8 -> conflict-free reads

// Scratch (no cudaMalloc allowed)
__device__ float g_emb[128 * 273 * 288];   // [B*C, 288]
__device__ float g_sc [128 * 270 * CP];    // [B, O, CP] scores -> tf32-rounded weights

// ---------------------------------------------------------------------------
// helpers
// ---------------------------------------------------------------------------
__device__ __forceinline__ uint32_t smem_u32(const void* p) {
    uint32_t a;
    asm("{ .reg .u64 t; cvta.to.shared.u64 t, %1; cvt.u32.u64 %0, t; }"
        : "=r"(a) : "l"(p));
    return a;
}
__device__ __forceinline__ void cp16(const void* dst, const void* src, bool full) {
    uint32_t d = smem_u32(dst);
    int sz = full ? 16 : 0;
    asm volatile("cp.async.cg.shared.global [%0], [%1], 16, %2;"
                 :: "r"(d), "l"(src), "r"(sz) : "memory");
}
#define CP_COMMIT() asm volatile("cp.async.commit_group;" ::: "memory")
#define CP_WAIT1()  asm volatile("cp.async.wait_group 1;" ::: "memory")
#define CP_WAIT0()  asm volatile("cp.async.wait_group 0;" ::: "memory")

__device__ __forceinline__ uint32_t f2tf(float x) {   // round-to-nearest tf32
    uint32_t r;
    asm("cvt.rna.tf32.f32 %0, %1;" : "=r"(r) : "f"(x));
    return r;
}
__device__ __forceinline__ void ldsm4(uint32_t r[4], uint32_t addr) {
    asm volatile("ldmatrix.sync.aligned.m8n8.x4.shared.b16 {%0,%1,%2,%3}, [%4];"
                 : "=r"(r[0]), "=r"(r[1]), "=r"(r[2]), "=r"(r[3]) : "r"(addr));
}
__device__ __forceinline__ void mma8(float c[4], const uint32_t a[4], const uint32_t b[2]) {
    asm volatile(
        "mma.sync.aligned.m16n8k8.row.col.f32.tf32.tf32.f32 "
        "{%0,%1,%2,%3}, {%4,%5,%6,%7}, {%8,%9}, {%0,%1,%2,%3};"
        : "+f"(c[0]), "+f"(c[1]), "+f"(c[2]), "+f"(c[3])
        : "r"(a[0]), "r"(a[1]), "r"(a[2]), "r"(a[3]), "r"(b[0]), "r"(b[1]));
}

// ---------------------------------------------------------------------------
// Kernel 1: Fourier embedding
// ---------------------------------------------------------------------------
__global__ void emb_kernel(const float* __restrict__ pos, int BC) {
    int row = blockIdx.x;
    if (row >= BC) return;
    int j = threadIdx.x;                    // 0..143
    float px = pos[2 * row]     + 0.2f;
    float py = pos[2 * row + 1] + 0.2f;
    const float w = 6.283185307179586f / 1.4f;
    int fi = j / NFREQ;
    int fj = j - fi * NFREQ;
    float loc = px * (w * (float)fi) + py * (w * (float)fj);
    float s, c;
    sincosf(loc, &s, &c);
    size_t base = (size_t)row * POS_DIM;
    g_emb[base + j]       = c;
    g_emb[base + 144 + j] = s;
}

// ---------------------------------------------------------------------------
// Kernel 2: scores[b,o,c] = sum_d heads[sid[b],o,d] * emb[b,c,d]
// Split-tf32 (hi/lo, 3 MMAs). Warp tile 32(o) x 32(c).
// ---------------------------------------------------------------------------
__global__ __launch_bounds__(256, 2)
void scores_mma(const float* __restrict__ heads, const int* __restrict__ sid,
                int B_, int C, int O) {
    extern __shared__ float sm[];
    float* As = sm;                 // [2][64][36]
    float* Es = sm + 2 * BM * AP;   // [2][128][36]

    int tid = threadIdx.x, wid = tid >> 5, lane = tid & 31;
    int g = lane >> 2, tig = lane & 3;
    int b = blockIdx.z, o0 = blockIdx.y * BM, c0 = blockIdx.x * BN;
    int mi = (wid >> 2) * 32, ni = (wid & 3) * 32;

    int a_row = (lane & 7) | (((lane >> 3) & 1) << 3);
    uint32_t a_loff = (uint32_t)(a_row * AP + (lane >> 4) * 4) * 4u;
    int e_row = ((lane >> 4) << 3) + (lane & 7);
    uint32_t e_loff = (uint32_t)(e_row * AP + ((lane >> 3) & 1) * 4) * 4u;

    const float* hb = heads + (size_t)sid[b] * O * POS_DIM;
    const float* eb = g_emb + (size_t)b * C * POS_DIM;

    float acc[2][4][4] = {};
    const int nch = POS_DIM / BK;   // 9

    auto load = [&](int j, int buf) {
        int k0 = j * BK;
        float* A = As + buf * BM * AP;
        float* E = Es + buf * BN * AP;
        #pragma unroll
        for (int r = 0; r < 2; r++) {
            int idx = tid + r * 256;
            int m = idx >> 3, k4 = (idx & 7) * 4;
            int go = o0 + m;
            cp16(A + m * AP + k4,
                 hb + (size_t)(go < O ? go : 0) * POS_DIM + k0 + k4, go < O);
        }
        #pragma unroll
        for (int r = 0; r < 4; r++) {
            int idx = tid + r * 256;
            int m = idx >> 3, k4 = (idx & 7) * 4;
            int gc = c0 + m;
            cp16(E + m * AP + k4,
                 eb + (size_t)(gc < C ? gc : 0) * POS_DIM + k0 + k4, gc < C);
        }
        CP_COMMIT();
    };

    load(0, 0);
    for (int j = 0; j < nch; j++) {
        int buf = j & 1;
        if (j + 1 < nch) { load(j + 1, buf ^ 1); CP_WAIT1(); }
        else             { CP_WAIT0(); }
        __syncthreads();
        uint32_t Au = smem_u32(As + buf * BM * AP);
        uint32_t Eu = smem_u32(Es + buf * BN * AP);
        #pragma unroll
        for (int kk = 0; kk < BK; kk += 8) {
            uint32_t ah[2][4], al[2][4];
            #pragma unroll
            for (int mt = 0; mt < 2; mt++) {
                uint32_t raw[4];
                ldsm4(raw, Au + (uint32_t)(((mi + mt * 16) * AP + kk) * 4) + a_loff);
                #pragma unroll
                for (int q = 0; q < 4; q++) {
                    float x = __uint_as_float(raw[q]);
                    ah[mt][q] = f2tf(x);
                    al[mt][q] = f2tf(x - __uint_as_float(ah[mt][q]));
                }
            }
            #pragma unroll
            for (int p = 0; p < 2; p++) {
                uint32_t raw[4];
                ldsm4(raw, Eu + (uint32_t)(((ni + p * 16) * AP + kk) * 4) + e_loff);
                #pragma unroll
                for (int h = 0; h < 2; h++) {
                    int nt = p * 2 + h;
                    uint32_t bh[2], bl[2];
                    #pragma unroll
                    for (int q = 0; q < 2; q++) {
                        float y = __uint_as_float(raw[h * 2 + q]);
                        bh[q] = f2tf(y);
                        bl[q] = f2tf(y - __uint_as_float(bh[q]));
                    }
                    #pragma unroll
                    for (int mt = 0; mt < 2; mt++) {
                        mma8(acc[mt][nt], ah[mt], bh);
                        mma8(acc[mt][nt], ah[mt], bl);
                        mma8(acc[mt][nt], al[mt], bh);
                    }
                }
            }
        }
        __syncthreads();
    }

    float* outb = g_sc + (size_t)b * O * CP;
    #pragma unroll
    for (int mt = 0; mt < 2; mt++) {
        int r0 = o0 + mi + mt * 16 + g;
        int r1 = r0 + 8;
        #pragma unroll
        for (int nt = 0; nt < 4; nt++) {
            int gc = c0 + ni + nt * 8 + tig * 2;
            if (gc < CP) {
                if (r0 < O)
                    *(float2*)(outb + (size_t)r0 * CP + gc) =
                        make_float2(acc[mt][nt][0], acc[mt][nt][1]);
                if (r1 < O)
                    *(float2*)(outb + (size_t)r1 * CP + gc) =
                        make_float2(acc[mt][nt][2], acc[mt][nt][3]);
            }
        }
    }
}

// ---------------------------------------------------------------------------
// Kernel 3: masked softmax over C; stores tf32-pre-rounded weights.
// Zero-fills cols [C, CP).
// ---------------------------------------------------------------------------
__global__ void softmax_kernel(const float* __restrict__ pos,
                               int B_, int C, int O, int rows) {
    int gwarp = (blockIdx.x * blockDim.x + threadIdx.x) >> 5;
    int lane  = threadIdx.x & 31;
    if (gwarp >= rows) return;
    int b = gwarp / O;
    float* row = g_sc + (size_t)gwarp * CP;
    const float* pb = pos + (size_t)b * C * 2;

    float v[9];
    float mx = -INFINITY;
    #pragma unroll
    for (int i = 0; i < 9; i++) {
        int c = lane + i * 32;
        float val = -INFINITY;
        if (c < C) {
            val = row[c];
            float px = pb[2 * c], py = pb[2 * c + 1];
            if (px == -0.1f && py == -0.1f) val = -INFINITY;
        }
        v[i] = val;
        mx = fmaxf(mx, val);
    }
    #pragma unroll
    for (int s = 16; s > 0; s >>= 1)
        mx = fmaxf(mx, __shfl_xor_sync(0xffffffffu, mx, s));

    float sum = 0.f;
    #pragma unroll
    for (int i = 0; i < 9; i++) {
        float e = expf(v[i] - mx);
        v[i] = e;
        sum += (lane + i * 32 < C) ? e : 0.f;
    }
    #pragma unroll
    for (int s = 16; s > 0; s >>= 1)
        sum += __shfl_xor_sync(0xffffffffu, sum, s);
    float inv = 1.f / sum;

    #pragma unroll
    for (int i = 0; i < 9; i++) {
        int c = lane + i * 32;
        if (c < C)       row[c] = __uint_as_float(f2tf(v[i] * inv));
        else if (c < CP) row[c] = 0.f;
    }
}

// ---------------------------------------------------------------------------
// Kernel 4 (dominant): out[b,o,t] = sum_c W[b,o,c] * meg[b,c,t]
// All-ldmatrix inner loop: A = pre-rounded weights (K-major), B = meg chunk
// transposed in-smem to [t][k] K-major + tf32-rounded during transpose.
// Inner per k-slice: 2 LDSM(A) + 2 LDSM(B) + 8 HMMA, no LDS/cvt.
// ---------------------------------------------------------------------------
__global__ __launch_bounds__(256, 3)
void out_mma(const float* __restrict__ meg, float* __restrict__ out,
             int B_, int C, int T, int O) {
    extern __shared__ float sm[];
    float* As  = sm;                             // [2][64][36]
    float* Stg = sm + 2 * BM * AP;               // [2][32][136] raw meg chunk
    float* Bsm = sm + 2 * BM * AP + 2 * BK * SP; // [128][36] transposed+rounded

    int tid = threadIdx.x, wid = tid >> 5, lane = tid & 31;
    int g = lane >> 2, tig = lane & 3;
    int b = blockIdx.z, o0 = blockIdx.y * BM, t0 = blockIdx.x * BN;
    int mi = (wid >> 2) * 32, ni = (wid & 3) * 32;

    int a_row = (lane & 7) | (((lane >> 3) & 1) << 3);
    uint32_t a_loff = (uint32_t)(a_row * AP + (lane >> 4) * 4) * 4u;
    int e_row = ((lane >> 4) << 3) + (lane & 7);
    uint32_t b_loff = (uint32_t)(e_row * AP + ((lane >> 3) & 1) * 4) * 4u;

    // transpose ownership: thread -> t-column tt, k-half kh
    int tt = tid & 127, kh = (tid >> 7) * 16;

    const float* wb = g_sc + (size_t)b * O * CP;
    const float* mb = meg  + (size_t)b * C * T;

    float acc[2][4][4] = {};
    const int nch = CP / BK;   // 9

    auto load = [&](int j, int buf) {
        int k0 = j * BK;
        float* A = As  + buf * BM * AP;
        float* S = Stg + buf * BK * SP;
        #pragma unroll
        for (int r = 0; r < 2; r++) {          // A: 64 x 32 = 512 cp16
            int idx = tid + r * 256;
            int m = idx >> 3, k4 = (idx & 7) * 4;
            int go = o0 + m;
            cp16(A + m * AP + k4,
                 wb + (size_t)(go < O ? go : 0) * CP + k0 + k4, go < O);
        }
        #pragma unroll
        for (int r = 0; r < 4; r++) {          // meg: 32 x 128 = 1024 cp16
            int idx = tid + r * 256;
            int c = idx >> 5, t4 = (idx & 31) * 4;
            int gc = k0 + c;
            cp16(S + c * SP + t4,
                 mb + (size_t)(gc < C ? gc : 0) * T + t0 + t4, gc < C);
        }
        CP_COMMIT();
    };

    load(0, 0);
    for (int j = 0; j < nch; j++) {
        int buf = j & 1;
        if (j + 1 < nch) { load(j + 1, buf ^ 1); CP_WAIT1(); }
        else             { CP_WAIT0(); }
        __syncthreads();   // chunk j staged; all warps past last compute

        // transpose + pre-round: Stg[buf][k][t] -> Bsm[t][k]
        const float* S = Stg + buf * BK * SP;
        #pragma unroll
        for (int kb = 0; kb < 4; kb++) {
            int k0 = kh + kb * 4;
            float4 v;
            v.x = __uint_as_float(f2tf(S[(k0 + 0) * SP + tt]));
            v.y = __uint_as_float(f2tf(S[(k0 + 1) * SP + tt]));
            v.z = __uint_as_float(f2tf(S[(k0 + 2) * SP + tt]));
            v.w = __uint_as_float(f2tf(S[(k0 + 3) * SP + tt]));
            *(float4*)(Bsm + tt * AP + k0) = v;
        }
        __syncthreads();   // Bsm ready

        uint32_t Au = smem_u32(As + buf * BM * AP);
        uint32_t Bu = smem_u32(Bsm);
        #pragma unroll
        for (int kk = 0; kk < BK; kk += 8) {
            uint32_t a[2][4], bfr[2][4];
            #pragma unroll
            for (int mt = 0; mt < 2; mt++)
                ldsm4(a[mt], Au + (uint32_t)(((mi + mt * 16) * AP + kk) * 4) + a_loff);
            #pragma unroll
            for (int p = 0; p < 2; p++)
                ldsm4(bfr[p], Bu + (uint32_t)(((ni + p * 16) * AP + kk) * 4) + b_loff);
            #pragma unroll
            for (int mt = 0; mt < 2; mt++)
                #pragma unroll
                for (int p = 0; p < 2; p++) {
                    mma8(acc[mt][p * 2 + 0], a[mt], &bfr[p][0]);
                    mma8(acc[mt][p * 2 + 1], a[mt], &bfr[p][2]);
                }
        }
        __syncthreads();   // all warps done with Bsm before next transpose
    }

    #pragma unroll
    for (int mt = 0; mt < 2; mt++) {
        int r0 = o0 + mi + mt * 16 + g;
        int r1 = r0 + 8;
        #pragma unroll
        for (int nt = 0; nt < 4; nt++) {
            int col = t0 + ni + nt * 8 + tig * 2;
            if (r0 < O)
                *(float2*)(out + ((size_t)b * O + r0) * T + col) =
                    make_float2(acc[mt][nt][0], acc[mt][nt][1]);
            if (r1 < O)
                *(float2*)(out + ((size_t)b * O + r1) * T + col) =
                    make_float2(acc[mt][nt][2], acc[mt][nt][3]);
        }
    }
}

// ---------------------------------------------------------------------------
// Launch. Inputs: meg f32 [B,C,T], positions f32 [B,C,2], subject_ids i32 [B],
// heads f32 [S,O,288]. Output f32 [B,O,T].
// ---------------------------------------------------------------------------
extern "C" void kernel_launch(void* const* d_in, const int* in_sizes, int n_in,
                              void* d_out, int out_size) {
    const float* meg   = (const float*)d_in[0];
    const float* pos   = (const float*)d_in[1];
    const int*   sid   = (const int*)  d_in[2];
    const float* heads = (const float*)d_in[3];
    float* out = (float*)d_out;

    int B = in_sizes[2];
    int C = in_sizes[1] / (2 * B);
    int T = in_sizes[0] / (B * C);
    int O = out_size / (B * T);

    const int smem_sc  = 2 * BM * AP * 4 + 2 * BN * AP * 4;                  // 55296 B
    const int smem_out = 2 * BM * AP * 4 + 2 * BK * SP * 4 + BN * AP * 4;    // 71680 B
    cudaFuncSetAttribute(scores_mma, cudaFuncAttributeMaxDynamicSharedMemorySize, smem_sc);
    cudaFuncSetAttribute(out_mma,    cudaFuncAttributeMaxDynamicSharedMemorySize, smem_out);

    // 1) Fourier embedding
    emb_kernel<<<B * C, 144>>>(pos, B * C);

    // 2) scores = heads[sid] @ emb^T  (split-tf32, ldmatrix fragments)
    dim3 gs((C + BN - 1) / BN, (O + BM - 1) / BM, B);
    scores_mma<<<gs, 256, smem_sc>>>(heads, sid, B, C, O);

    // 3) masked softmax (+ tf32 pre-round + zero pad to CP)
    int rows = B * O;
    int nblk = (rows * 32 + 255) / 256;
    softmax_kernel<<<nblk, 256>>>(pos, B, C, O, rows);

    // 4) out = weights @ meg  (all-ldmatrix tf32 mma, in-smem transpose)
    dim3 gd(T / BN, (O + BM - 1) / BM, B);
    out_mma<<<gd, 256, smem_out>>>(meg, out, B, C, T, O);
}

// round 10
// speedup vs baseline: 1.0724x; 1.0724x over previous
#include <cuda_runtime.h>
#include <math.h>
#include <stdint.h>

#define POS_DIM 288
#define NFREQ   12
#define CP      288      // padded pitch for weights rows (16B-aligned)
#define BM      64       // m-tile (o): 5 blocks over O=270
#define BN      128
#define BK      32
#define AP      36       // K-major smem pitch: ldmatrix + scalar reads conflict-free
#define BP      136      // meg smem pitch: 136 % 32 == 8 -> bank = 8*tig+g, bijective

// Scratch (no cudaMalloc allowed)
__device__ float g_emb[128 * 273 * 288];   // [B*C, 288]
__device__ float g_sc [128 * 270 * CP];    // [B, O, CP] scores -> tf32-rounded weights

// ---------------------------------------------------------------------------
// helpers
// ---------------------------------------------------------------------------
__device__ __forceinline__ uint32_t smem_u32(const void* p) {
    uint32_t a;
    asm("{ .reg .u64 t; cvta.to.shared.u64 t, %1; cvt.u32.u64 %0, t; }"
        : "=r"(a) : "l"(p));
    return a;
}
__device__ __forceinline__ void cp16(const void* dst, const void* src, bool full) {
    uint32_t d = smem_u32(dst);
    int sz = full ? 16 : 0;
    asm volatile("cp.async.cg.shared.global [%0], [%1], 16, %2;"
                 :: "r"(d), "l"(src), "r"(sz) : "memory");
}
#define CP_COMMIT() asm volatile("cp.async.commit_group;" ::: "memory")
#define CP_WAIT1()  asm volatile("cp.async.wait_group 1;" ::: "memory")
#define CP_WAIT0()  asm volatile("cp.async.wait_group 0;" ::: "memory")

__device__ __forceinline__ uint32_t f2tf(float x) {   // round-to-nearest tf32
    uint32_t r;
    asm("cvt.rna.tf32.f32 %0, %1;" : "=r"(r) : "f"(x));
    return r;
}
__device__ __forceinline__ void ldsm4(uint32_t r[4], uint32_t addr) {
    asm volatile("ldmatrix.sync.aligned.m8n8.x4.shared.b16 {%0,%1,%2,%3}, [%4];"
                 : "=r"(r[0]), "=r"(r[1]), "=r"(r[2]), "=r"(r[3]) : "r"(addr));
}
__device__ __forceinline__ void mma8(float c[4], const uint32_t a[4], const uint32_t b[2]) {
    asm volatile(
        "mma.sync.aligned.m16n8k8.row.col.f32.tf32.tf32.f32 "
        "{%0,%1,%2,%3}, {%4,%5,%6,%7}, {%8,%9}, {%0,%1,%2,%3};"
        : "+f"(c[0]), "+f"(c[1]), "+f"(c[2]), "+f"(c[3])
        : "r"(a[0]), "r"(a[1]), "r"(a[2]), "r"(a[3]), "r"(b[0]), "r"(b[1]));
}

// ---------------------------------------------------------------------------
// Kernel 1: Fourier embedding
// ---------------------------------------------------------------------------
__global__ void emb_kernel(const float* __restrict__ pos, int BC) {
    int row = blockIdx.x;
    if (row >= BC) return;
    int j = threadIdx.x;                    // 0..143
    float px = pos[2 * row]     + 0.2f;
    float py = pos[2 * row + 1] + 0.2f;
    const float w = 6.283185307179586f / 1.4f;
    int fi = j / NFREQ;
    int fj = j - fi * NFREQ;
    float loc = px * (w * (float)fi) + py * (w * (float)fj);
    float s, c;
    sincosf(loc, &s, &c);
    size_t base = (size_t)row * POS_DIM;
    g_emb[base + j]       = c;
    g_emb[base + 144 + j] = s;
}

// ---------------------------------------------------------------------------
// Kernel 2: scores[b,o,c] = sum_d heads[sid[b],o,d] * emb[b,c,d]
// Split-tf32 (hi/lo, 3 MMAs). Warp tile 32(o) x 32(c). (unchanged from R8)
// ---------------------------------------------------------------------------
__global__ __launch_bounds__(256, 2)
void scores_mma(const float* __restrict__ heads, const int* __restrict__ sid,
                int B_, int C, int O) {
    extern __shared__ float sm[];
    float* As = sm;                 // [2][64][36]
    float* Es = sm + 2 * BM * AP;   // [2][128][36]

    int tid = threadIdx.x, wid = tid >> 5, lane = tid & 31;
    int g = lane >> 2, tig = lane & 3;
    int b = blockIdx.z, o0 = blockIdx.y * BM, c0 = blockIdx.x * BN;
    int mi = (wid >> 2) * 32, ni = (wid & 3) * 32;

    int a_row = (lane & 7) | (((lane >> 3) & 1) << 3);
    uint32_t a_loff = (uint32_t)(a_row * AP + (lane >> 4) * 4) * 4u;
    int e_row = ((lane >> 4) << 3) + (lane & 7);
    uint32_t e_loff = (uint32_t)(e_row * AP + ((lane >> 3) & 1) * 4) * 4u;

    const float* hb = heads + (size_t)sid[b] * O * POS_DIM;
    const float* eb = g_emb + (size_t)b * C * POS_DIM;

    float acc[2][4][4] = {};
    const int nch = POS_DIM / BK;   // 9

    auto load = [&](int j, int buf) {
        int k0 = j * BK;
        float* A = As + buf * BM * AP;
        float* E = Es + buf * BN * AP;
        #pragma unroll
        for (int r = 0; r < 2; r++) {
            int idx = tid + r * 256;
            int m = idx >> 3, k4 = (idx & 7) * 4;
            int go = o0 + m;
            cp16(A + m * AP + k4,
                 hb + (size_t)(go < O ? go : 0) * POS_DIM + k0 + k4, go < O);
        }
        #pragma unroll
        for (int r = 0; r < 4; r++) {
            int idx = tid + r * 256;
            int m = idx >> 3, k4 = (idx & 7) * 4;
            int gc = c0 + m;
            cp16(E + m * AP + k4,
                 eb + (size_t)(gc < C ? gc : 0) * POS_DIM + k0 + k4, gc < C);
        }
        CP_COMMIT();
    };

    load(0, 0);
    for (int j = 0; j < nch; j++) {
        int buf = j & 1;
        if (j + 1 < nch) { load(j + 1, buf ^ 1); CP_WAIT1(); }
        else             { CP_WAIT0(); }
        __syncthreads();
        uint32_t Au = smem_u32(As + buf * BM * AP);
        uint32_t Eu = smem_u32(Es + buf * BN * AP);
        #pragma unroll
        for (int kk = 0; kk < BK; kk += 8) {
            uint32_t ah[2][4], al[2][4];
            #pragma unroll
            for (int mt = 0; mt < 2; mt++) {
                uint32_t raw[4];
                ldsm4(raw, Au + (uint32_t)(((mi + mt * 16) * AP + kk) * 4) + a_loff);
                #pragma unroll
                for (int q = 0; q < 4; q++) {
                    float x = __uint_as_float(raw[q]);
                    ah[mt][q] = f2tf(x);
                    al[mt][q] = f2tf(x - __uint_as_float(ah[mt][q]));
                }
            }
            #pragma unroll
            for (int p = 0; p < 2; p++) {
                uint32_t raw[4];
                ldsm4(raw, Eu + (uint32_t)(((ni + p * 16) * AP + kk) * 4) + e_loff);
                #pragma unroll
                for (int h = 0; h < 2; h++) {
                    int nt = p * 2 + h;
                    uint32_t bh[2], bl[2];
                    #pragma unroll
                    for (int q = 0; q < 2; q++) {
                        float y = __uint_as_float(raw[h * 2 + q]);
                        bh[q] = f2tf(y);
                        bl[q] = f2tf(y - __uint_as_float(bh[q]));
                    }
                    #pragma unroll
                    for (int mt = 0; mt < 2; mt++) {
                        mma8(acc[mt][nt], ah[mt], bh);
                        mma8(acc[mt][nt], ah[mt], bl);
                        mma8(acc[mt][nt], al[mt], bh);
                    }
                }
            }
        }
        __syncthreads();
    }

    float* outb = g_sc + (size_t)b * O * CP;
    #pragma unroll
    for (int mt = 0; mt < 2; mt++) {
        int r0 = o0 + mi + mt * 16 + g;
        int r1 = r0 + 8;
        #pragma unroll
        for (int nt = 0; nt < 4; nt++) {
            int gc = c0 + ni + nt * 8 + tig * 2;
            if (gc < CP) {
                if (r0 < O)
                    *(float2*)(outb + (size_t)r0 * CP + gc) =
                        make_float2(acc[mt][nt][0], acc[mt][nt][1]);
                if (r1 < O)
                    *(float2*)(outb + (size_t)r1 * CP + gc) =
                        make_float2(acc[mt][nt][2], acc[mt][nt][3]);
            }
        }
    }
}

// ---------------------------------------------------------------------------
// Kernel 3: masked softmax over C; stores tf32-pre-rounded weights.
// Zero-fills cols [C, CP).
// ---------------------------------------------------------------------------
__global__ void softmax_kernel(const float* __restrict__ pos,
                               int B_, int C, int O, int rows) {
    int gwarp = (blockIdx.x * blockDim.x + threadIdx.x) >> 5;
    int lane  = threadIdx.x & 31;
    if (gwarp >= rows) return;
    int b = gwarp / O;
    float* row = g_sc + (size_t)gwarp * CP;
    const float* pb = pos + (size_t)b * C * 2;

    float v[9];
    float mx = -INFINITY;
    #pragma unroll
    for (int i = 0; i < 9; i++) {
        int c = lane + i * 32;
        float val = -INFINITY;
        if (c < C) {
            val = row[c];
            float px = pb[2 * c], py = pb[2 * c + 1];
            if (px == -0.1f && py == -0.1f) val = -INFINITY;
        }
        v[i] = val;
        mx = fmaxf(mx, val);
    }
    #pragma unroll
    for (int s = 16; s > 0; s >>= 1)
        mx = fmaxf(mx, __shfl_xor_sync(0xffffffffu, mx, s));

    float sum = 0.f;
    #pragma unroll
    for (int i = 0; i < 9; i++) {
        float e = expf(v[i] - mx);
        v[i] = e;
        sum += (lane + i * 32 < C) ? e : 0.f;
    }
    #pragma unroll
    for (int s = 16; s > 0; s >>= 1)
        sum += __shfl_xor_sync(0xffffffffu, sum, s);
    float inv = 1.f / sum;

    #pragma unroll
    for (int i = 0; i < 9; i++) {
        int c = lane + i * 32;
        if (c < C)       row[c] = __uint_as_float(f2tf(v[i] * inv));
        else if (c < CP) row[c] = 0.f;
    }
}

// ---------------------------------------------------------------------------
// Kernel 4 (dominant): out[b,o,t] = sum_c W[b,o,c] * meg[b,c,t]
// R8 structure, rebalanced warp tile: each warp covers 64(m) x 16(n).
// Per k-slice per warp: 4 LDSM(A) + 4 LDS(B) + 4 cvt + 8 HMMA
// (block-level LDS & cvt halved vs R8's 32x32 warp tile).
// ---------------------------------------------------------------------------
__global__ __launch_bounds__(256, 3)
void out_mma(const float* __restrict__ meg, float* __restrict__ out,
             int B_, int C, int T, int O) {
    extern __shared__ float sm[];
    float* As = sm;                 // [2][64][36]
    float* Bs = sm + 2 * BM * AP;   // [2][32][136]

    int tid = threadIdx.x, wid = tid >> 5, lane = tid & 31;
    int g = lane >> 2, tig = lane & 3;
    int b = blockIdx.z, o0 = blockIdx.y * BM, t0 = blockIdx.x * BN;
    int ni = wid * 16;              // warp n-offset; m spans full BM=64

    int a_row = (lane & 7) | (((lane >> 3) & 1) << 3);
    uint32_t a_loff = (uint32_t)(a_row * AP + (lane >> 4) * 4) * 4u;

    const float* wb = g_sc + (size_t)b * O * CP;
    const float* mb = meg  + (size_t)b * C * T;

    float acc[4][2][4] = {};
    const int nch = CP / BK;   // 9

    auto load = [&](int j, int buf) {
        int k0 = j * BK;
        float* A  = As + buf * BM * AP;
        float* Bt = Bs + buf * BK * BP;
        #pragma unroll
        for (int r = 0; r < 2; r++) {          // A: 64 x 32 = 512 cp16
            int idx = tid + r * 256;
            int m = idx >> 3, k4 = (idx & 7) * 4;
            int go = o0 + m;
            cp16(A + m * AP + k4,
                 wb + (size_t)(go < O ? go : 0) * CP + k0 + k4, go < O);
        }
        #pragma unroll
        for (int r = 0; r < 4; r++) {          // B: 32 x 128 = 1024 cp16
            int idx = tid + r * 256;
            int c = idx >> 5, t4 = (idx & 31) * 4;
            int gc = k0 + c;
            cp16(Bt + c * BP + t4,
                 mb + (size_t)(gc < C ? gc : 0) * T + t0 + t4, gc < C);
        }
        CP_COMMIT();
    };

    load(0, 0);
    for (int j = 0; j < nch; j++) {
        int buf = j & 1;
        if (j + 1 < nch) { load(j + 1, buf ^ 1); CP_WAIT1(); }
        else             { CP_WAIT0(); }
        __syncthreads();
        uint32_t Au = smem_u32(As + buf * BM * AP);
        const float* Bt = Bs + buf * BK * BP;
        #pragma unroll
        for (int kk = 0; kk < BK; kk += 8) {
            uint32_t a[4][4], bf[2][2];
            #pragma unroll
            for (int mt = 0; mt < 4; mt++)
                ldsm4(a[mt], Au + (uint32_t)(((mt * 16) * AP + kk) * 4) + a_loff);
            #pragma unroll
            for (int nt = 0; nt < 2; nt++) {
                const float* bp = Bt + (kk + tig) * BP + ni + nt * 8 + g;
                bf[nt][0] = f2tf(bp[0]);
                bf[nt][1] = f2tf(bp[4 * BP]);
            }
            #pragma unroll
            for (int mt = 0; mt < 4; mt++)
                #pragma unroll
                for (int nt = 0; nt < 2; nt++)
                    mma8(acc[mt][nt], a[mt], bf[nt]);
        }
        __syncthreads();
    }

    #pragma unroll
    for (int mt = 0; mt < 4; mt++) {
        int r0 = o0 + mt * 16 + g;
        int r1 = r0 + 8;
        #pragma unroll
        for (int nt = 0; nt < 2; nt++) {
            int col = t0 + ni + nt * 8 + tig * 2;
            if (r0 < O)
                *(float2*)(out + ((size_t)b * O + r0) * T + col) =
                    make_float2(acc[mt][nt][0], acc[mt][nt][1]);
            if (r1 < O)
                *(float2*)(out + ((size_t)b * O + r1) * T + col) =
                    make_float2(acc[mt][nt][2], acc[mt][nt][3]);
        }
    }
}

// ---------------------------------------------------------------------------
// Launch. Inputs: meg f32 [B,C,T], positions f32 [B,C,2], subject_ids i32 [B],
// heads f32 [S,O,288]. Output f32 [B,O,T].
// ---------------------------------------------------------------------------
extern "C" void kernel_launch(void* const* d_in, const int* in_sizes, int n_in,
                              void* d_out, int out_size) {
    const float* meg   = (const float*)d_in[0];
    const float* pos   = (const float*)d_in[1];
    const int*   sid   = (const int*)  d_in[2];
    const float* heads = (const float*)d_in[3];
    float* out = (float*)d_out;

    int B = in_sizes[2];
    int C = in_sizes[1] / (2 * B);
    int T = in_sizes[0] / (B * C);
    int O = out_size / (B * T);

    const int smem_sc  = 2 * BM * AP * 4 + 2 * BN * AP * 4;   // 55296 B
    const int smem_out = 2 * BM * AP * 4 + 2 * BK * BP * 4;   // 53248 B
    cudaFuncSetAttribute(scores_mma, cudaFuncAttributeMaxDynamicSharedMemorySize, smem_sc);
    cudaFuncSetAttribute(out_mma,    cudaFuncAttributeMaxDynamicSharedMemorySize, smem_out);

    // 1) Fourier embedding
    emb_kernel<<<B * C, 144>>>(pos, B * C);

    // 2) scores = heads[sid] @ emb^T  (split-tf32, ldmatrix fragments)
    dim3 gs((C + BN - 1) / BN, (O + BM - 1) / BM, B);
    scores_mma<<<gs, 256, smem_sc>>>(heads, sid, B, C, O);

    // 3) masked softmax (+ tf32 pre-round + zero pad to CP)
    int rows = B * O;
    int nblk = (rows * 32 + 255) / 256;
    softmax_kernel<<<nblk, 256>>>(pos, B, C, O, rows);

    // 4) out = weights @ meg  (tf32 mma.sync, 64x16 warp tiles)
    dim3 gd(T / BN, (O + BM - 1) / BM, B);
    out_mma<<<gd, 256, smem_out>>>(meg, out, B, C, T, O);
}

// round 13
// speedup vs baseline: 1.3634x; 1.2713x over previous
#include <cuda_runtime.h>
#include <math.h>
#include <stdint.h>

#define POS_DIM 288
#define NFREQ   12
#define CP      288      // padded pitch for weights rows (16B-aligned)
#define BM      64       // m-tile (o): 5 blocks over O=270
#define BN      128      // scores n-tile (c)
#define ON      256      // out n-tile (t)
#define BK      32
#define AP      36       // K-major smem pitch: ldmatrix/scalar conflict-free
#define BP      264      // out meg pitch: 264 % 32 == 8 -> bank bijective

// Scratch (no cudaMalloc allowed)
__device__ float g_emb[128 * 273 * 288];   // [B*C, 288] tf32-pre-rounded
__device__ float g_sc [128 * 270 * CP];    // [B, O, CP] scores -> tf32-rounded weights

// ---------------------------------------------------------------------------
// helpers
// ---------------------------------------------------------------------------
__device__ __forceinline__ uint32_t smem_u32(const void* p) {
    uint32_t a;
    asm("{ .reg .u64 t; cvta.to.shared.u64 t, %1; cvt.u32.u64 %0, t; }"
        : "=r"(a) : "l"(p));
    return a;
}
__device__ __forceinline__ void cp16(const void* dst, const void* src, bool full) {
    uint32_t d = smem_u32(dst);
    int sz = full ? 16 : 0;
    asm volatile("cp.async.cg.shared.global [%0], [%1], 16, %2;"
                 :: "r"(d), "l"(src), "r"(sz) : "memory");
}
#define CP_COMMIT() asm volatile("cp.async.commit_group;" ::: "memory")
#define CP_WAIT1()  asm volatile("cp.async.wait_group 1;" ::: "memory")
#define CP_WAIT0()  asm volatile("cp.async.wait_group 0;" ::: "memory")

__device__ __forceinline__ uint32_t f2tf(float x) {   // round-to-nearest tf32
    uint32_t r;
    asm("cvt.rna.tf32.f32 %0, %1;" : "=r"(r) : "f"(x));
    return r;
}
__device__ __forceinline__ void ldsm4(uint32_t r[4], uint32_t addr) {
    asm volatile("ldmatrix.sync.aligned.m8n8.x4.shared.b16 {%0,%1,%2,%3}, [%4];"
                 : "=r"(r[0]), "=r"(r[1]), "=r"(r[2]), "=r"(r[3]) : "r"(addr));
}
__device__ __forceinline__ void mma8(float c[4], const uint32_t a[4], const uint32_t b[2]) {
    asm volatile(
        "mma.sync.aligned.m16n8k8.row.col.f32.tf32.tf32.f32 "
        "{%0,%1,%2,%3}, {%4,%5,%6,%7}, {%8,%9}, {%0,%1,%2,%3};"
        : "+f"(c[0]), "+f"(c[1]), "+f"(c[2]), "+f"(c[3])
        : "r"(a[0]), "r"(a[1]), "r"(a[2]), "r"(a[3]), "r"(b[0]), "r"(b[1]));
}

// ---------------------------------------------------------------------------
// Kernel 1: Fourier embedding (stores tf32-pre-rounded values)
// ---------------------------------------------------------------------------
__global__ void emb_kernel(const float* __restrict__ pos, int BC) {
    int row = blockIdx.x;
    if (row >= BC) return;
    int j = threadIdx.x;                    // 0..143
    float px = pos[2 * row]     + 0.2f;
    float py = pos[2 * row + 1] + 0.2f;
    const float w = 6.283185307179586f / 1.4f;
    int fi = j / NFREQ;
    int fj = j - fi * NFREQ;
    float loc = px * (w * (float)fi) + py * (w * (float)fj);
    float s, c;
    sincosf(loc, &s, &c);
    size_t base = (size_t)row * POS_DIM;
    g_emb[base + j]       = __uint_as_float(f2tf(c));
    g_emb[base + 144 + j] = __uint_as_float(f2tf(s));
}

// ---------------------------------------------------------------------------
// Kernel 2: scores[b,o,c] = sum_d heads[sid[b],o,d] * emb[b,c,d]
// Single-pass tf32 (rna): emb pre-rounded (raw ldmatrix), heads cvt in-loop.
// Warp tile 32(o) x 32(c).
// ---------------------------------------------------------------------------
__global__ __launch_bounds__(256, 2)
void scores_mma(const float* __restrict__ heads, const int* __restrict__ sid,
                int B_, int C, int O) {
    extern __shared__ float sm[];
    float* As = sm;                 // [2][64][36]
    float* Es = sm + 2 * BM * AP;   // [2][128][36]

    int tid = threadIdx.x, wid = tid >> 5, lane = tid & 31;
    int g = lane >> 2, tig = lane & 3;
    int b = blockIdx.z, o0 = blockIdx.y * BM, c0 = blockIdx.x * BN;
    int mi = (wid >> 2) * 32, ni = (wid & 3) * 32;

    int a_row = (lane & 7) | (((lane >> 3) & 1) << 3);
    uint32_t a_loff = (uint32_t)(a_row * AP + (lane >> 4) * 4) * 4u;
    int e_row = ((lane >> 4) << 3) + (lane & 7);
    uint32_t e_loff = (uint32_t)(e_row * AP + ((lane >> 3) & 1) * 4) * 4u;

    const float* hb = heads + (size_t)sid[b] * O * POS_DIM;
    const float* eb = g_emb + (size_t)b * C * POS_DIM;

    float acc[2][4][4] = {};
    const int nch = POS_DIM / BK;   // 9

    auto load = [&](int j, int buf) {
        int k0 = j * BK;
        float* A = As + buf * BM * AP;
        float* E = Es + buf * BN * AP;
        #pragma unroll
        for (int r = 0; r < 2; r++) {
            int idx = tid + r * 256;
            int m = idx >> 3, k4 = (idx & 7) * 4;
            int go = o0 + m;
            cp16(A + m * AP + k4,
                 hb + (size_t)(go < O ? go : 0) * POS_DIM + k0 + k4, go < O);
        }
        #pragma unroll
        for (int r = 0; r < 4; r++) {
            int idx = tid + r * 256;
            int m = idx >> 3, k4 = (idx & 7) * 4;
            int gc = c0 + m;
            cp16(E + m * AP + k4,
                 eb + (size_t)(gc < C ? gc : 0) * POS_DIM + k0 + k4, gc < C);
        }
        CP_COMMIT();
    };

    load(0, 0);
    for (int j = 0; j < nch; j++) {
        int buf = j & 1;
        if (j + 1 < nch) { load(j + 1, buf ^ 1); CP_WAIT1(); }
        else             { CP_WAIT0(); }
        __syncthreads();
        uint32_t Au = smem_u32(As + buf * BM * AP);
        uint32_t Eu = smem_u32(Es + buf * BN * AP);
        #pragma unroll
        for (int kk = 0; kk < BK; kk += 8) {
            uint32_t a[2][4];
            #pragma unroll
            for (int mt = 0; mt < 2; mt++) {
                uint32_t raw[4];
                ldsm4(raw, Au + (uint32_t)(((mi + mt * 16) * AP + kk) * 4) + a_loff);
                #pragma unroll
                for (int q = 0; q < 4; q++)
                    a[mt][q] = f2tf(__uint_as_float(raw[q]));
            }
            #pragma unroll
            for (int p = 0; p < 2; p++) {
                uint32_t raw[4];   // emb pre-rounded: feed raw bits
                ldsm4(raw, Eu + (uint32_t)(((ni + p * 16) * AP + kk) * 4) + e_loff);
                #pragma unroll
                for (int mt = 0; mt < 2; mt++) {
                    mma8(acc[mt][p * 2 + 0], a[mt], &raw[0]);
                    mma8(acc[mt][p * 2 + 1], a[mt], &raw[2]);
                }
            }
        }
        __syncthreads();
    }

    float* outb = g_sc + (size_t)b * O * CP;
    #pragma unroll
    for (int mt = 0; mt < 2; mt++) {
        int r0 = o0 + mi + mt * 16 + g;
        int r1 = r0 + 8;
        #pragma unroll
        for (int nt = 0; nt < 4; nt++) {
            int gc = c0 + ni + nt * 8 + tig * 2;
            if (gc < CP) {
                if (r0 < O)
                    *(float2*)(outb + (size_t)r0 * CP + gc) =
                        make_float2(acc[mt][nt][0], acc[mt][nt][1]);
                if (r1 < O)
                    *(float2*)(outb + (size_t)r1 * CP + gc) =
                        make_float2(acc[mt][nt][2], acc[mt][nt][3]);
            }
        }
    }
}

// ---------------------------------------------------------------------------
// Kernel 3: masked softmax over C; stores tf32-pre-rounded weights.
// Zero-fills cols [C, CP).
// ---------------------------------------------------------------------------
__global__ void softmax_kernel(const float* __restrict__ pos,
                               int B_, int C, int O, int rows) {
    int gwarp = (blockIdx.x * blockDim.x + threadIdx.x) >> 5;
    int lane  = threadIdx.x & 31;
    if (gwarp >= rows) return;
    int b = gwarp / O;
    float* row = g_sc + (size_t)gwarp * CP;
    const float* pb = pos + (size_t)b * C * 2;

    float v[9];
    float mx = -INFINITY;
    #pragma unroll
    for (int i = 0; i < 9; i++) {
        int c = lane + i * 32;
        float val = -INFINITY;
        if (c < C) {
            val = row[c];
            float px = pb[2 * c], py = pb[2 * c + 1];
            if (px == -0.1f && py == -0.1f) val = -INFINITY;
        }
        v[i] = val;
        mx = fmaxf(mx, val);
    }
    #pragma unroll
    for (int s = 16; s > 0; s >>= 1)
        mx = fmaxf(mx, __shfl_xor_sync(0xffffffffu, mx, s));

    float sum = 0.f;
    #pragma unroll
    for (int i = 0; i < 9; i++) {
        float e = expf(v[i] - mx);
        v[i] = e;
        sum += (lane + i * 32 < C) ? e : 0.f;
    }
    #pragma unroll
    for (int s = 16; s > 0; s >>= 1)
        sum += __shfl_xor_sync(0xffffffffu, sum, s);
    float inv = 1.f / sum;

    #pragma unroll
    for (int i = 0; i < 9; i++) {
        int c = lane + i * 32;
        if (c < C)       row[c] = __uint_as_float(f2tf(v[i] * inv));
        else if (c < CP) row[c] = 0.f;
    }
}

// ---------------------------------------------------------------------------
// Kernel 4 (dominant): out[b,o,t] = sum_c W[b,o,c] * meg[b,c,t]
// Block tile 64(o) x 256(t), warp tile 32x64 (2x4 warp grid) — minimizes
// smem bytes/flop: 136KB per chunk for 2x the old work (-23%/unit).
// ---------------------------------------------------------------------------
__global__ __launch_bounds__(256, 2)
void out_mma(const float* __restrict__ meg, float* __restrict__ out,
             int B_, int C, int T, int O) {
    extern __shared__ float sm[];
    float* As = sm;                 // [2][64][36]
    float* Bs = sm + 2 * BM * AP;   // [2][32][264]

    int tid = threadIdx.x, wid = tid >> 5, lane = tid & 31;
    int g = lane >> 2, tig = lane & 3;
    int b = blockIdx.z, o0 = blockIdx.y * BM, t0 = blockIdx.x * ON;
    int mi = (wid >> 2) * 32, ni = (wid & 3) * 64;

    int a_row = (lane & 7) | (((lane >> 3) & 1) << 3);
    uint32_t a_loff = (uint32_t)(a_row * AP + (lane >> 4) * 4) * 4u;

    const float* wb = g_sc + (size_t)b * O * CP;
    const float* mb = meg  + (size_t)b * C * T;

    float acc[2][8][4] = {};
    const int nch = CP / BK;   // 9

    auto load = [&](int j, int buf) {
        int k0 = j * BK;
        float* A  = As + buf * BM * AP;
        float* Bt = Bs + buf * BK * BP;
        #pragma unroll
        for (int r = 0; r < 2; r++) {          // A: 64 x 32 = 512 cp16
            int idx = tid + r * 256;
            int m = idx >> 3, k4 = (idx & 7) * 4;
            int go = o0 + m;
            cp16(A + m * AP + k4,
                 wb + (size_t)(go < O ? go : 0) * CP + k0 + k4, go < O);
        }
        #pragma unroll
        for (int r = 0; r < 8; r++) {          // B: 32 x 256 = 2048 cp16
            int idx = tid + r * 256;
            int c = idx >> 6, t4 = (idx & 63) * 4;
            int gc = k0 + c;
            cp16(Bt + c * BP + t4,
                 mb + (size_t)(gc < C ? gc : 0) * T + t0 + t4, gc < C);
        }
        CP_COMMIT();
    };

    load(0, 0);
    for (int j = 0; j < nch; j++) {
        int buf = j & 1;
        if (j + 1 < nch) { load(j + 1, buf ^ 1); CP_WAIT1(); }
        else             { CP_WAIT0(); }
        __syncthreads();
        uint32_t Au = smem_u32(As + buf * BM * AP);
        const float* Bt = Bs + buf * BK * BP;
        #pragma unroll
        for (int kk = 0; kk < BK; kk += 8) {
            uint32_t a[2][4], bf[8][2];
            #pragma unroll
            for (int mt = 0; mt < 2; mt++)
                ldsm4(a[mt], Au + (uint32_t)(((mi + mt * 16) * AP + kk) * 4) + a_loff);
            #pragma unroll
            for (int nt = 0; nt < 8; nt++) {
                const float* bp = Bt + (kk + tig) * BP + ni + nt * 8 + g;
                bf[nt][0] = f2tf(bp[0]);
                bf[nt][1] = f2tf(bp[4 * BP]);
            }
            #pragma unroll
            for (int mt = 0; mt < 2; mt++)
                #pragma unroll
                for (int nt = 0; nt < 8; nt++)
                    mma8(acc[mt][nt], a[mt], bf[nt]);
        }
        __syncthreads();
    }

    #pragma unroll
    for (int mt = 0; mt < 2; mt++) {
        int r0 = o0 + mi + mt * 16 + g;
        int r1 = r0 + 8;
        #pragma unroll
        for (int nt = 0; nt < 8; nt++) {
            int col = t0 + ni + nt * 8 + tig * 2;
            if (r0 < O)
                *(float2*)(out + ((size_t)b * O + r0) * T + col) =
                    make_float2(acc[mt][nt][0], acc[mt][nt][1]);
            if (r1 < O)
                *(float2*)(out + ((size_t)b * O + r1) * T + col) =
                    make_float2(acc[mt][nt][2], acc[mt][nt][3]);
        }
    }
}

// ---------------------------------------------------------------------------
// Launch. Inputs: meg f32 [B,C,T], positions f32 [B,C,2], subject_ids i32 [B],
// heads f32 [S,O,288]. Output f32 [B,O,T].
// ---------------------------------------------------------------------------
extern "C" void kernel_launch(void* const* d_in, const int* in_sizes, int n_in,
                              void* d_out, int out_size) {
    const float* meg   = (const float*)d_in[0];
    const float* pos   = (const float*)d_in[1];
    const int*   sid   = (const int*)  d_in[2];
    const float* heads = (const float*)d_in[3];
    float* out = (float*)d_out;

    int B = in_sizes[2];
    int C = in_sizes[1] / (2 * B);
    int T = in_sizes[0] / (B * C);
    int O = out_size / (B * T);

    const int smem_sc  = 2 * BM * AP * 4 + 2 * BN * AP * 4;   // 55296 B
    const int smem_out = 2 * BM * AP * 4 + 2 * BK * BP * 4;   // 86016 B
    cudaFuncSetAttribute(scores_mma, cudaFuncAttributeMaxDynamicSharedMemorySize, smem_sc);
    cudaFuncSetAttribute(out_mma,    cudaFuncAttributeMaxDynamicSharedMemorySize, smem_out);

    // 1) Fourier embedding (tf32-pre-rounded)
    emb_kernel<<<B * C, 144>>>(pos, B * C);

    // 2) scores = heads[sid] @ emb^T  (single-pass tf32)
    dim3 gs((C + BN - 1) / BN, (O + BM - 1) / BM, B);
    scores_mma<<<gs, 256, smem_sc>>>(heads, sid, B, C, O);

    // 3) masked softmax (+ tf32 pre-round + zero pad to CP)
    int rows = B * O;
    int nblk = (rows * 32 + 255) / 256;
    softmax_kernel<<<nblk, 256>>>(pos, B, C, O, rows);

    // 4) out = weights @ meg  (tf32 mma.sync, 64x256 block, 32x64 warps)
    dim3 gd(T / ON, (O + BM - 1) / BM, B);
    out_mma<<<gd, 256, smem_out>>>(meg, out, B, C, T, O);
}

// round 16
// speedup vs baseline: 1.8479x; 1.3553x over previous
#include <cuda_runtime.h>
#include <cuda_fp16.h>
#include <math.h>
#include <stdint.h>

#define POS_DIM 288
#define NFREQ   12
#define CP      288      // padded K pitch for weights (16B-aligned fp16 rows)
#define BM      64       // m-tile (o): 5 blocks over O=270
#define BN      128      // scores n-tile (c)
#define ON      128      // out n-tile (t)
#define BK      32
#define APH     40       // fp16 K-major pitch (80B rows)
#define BPH     136      // fp16 [k][t] pitch (272B rows)

// Scratch (no cudaMalloc allowed) — referenced ONLY inside device code
__device__ __half g_megh  [128 * 273 * 2048];  // meg pre-converted to fp16
__device__ __half g_headsh[200 * 270 * 288];   // heads pre-converted to fp16
__device__ __half g_embh  [128 * 273 * 288];   // fourier emb, fp16
__device__ float  g_sc    [128 * 270 * CP];    // raw scores (f32 for softmax)
__device__ __half g_w     [128 * 270 * CP];    // softmax weights, fp16, padded

// ---------------------------------------------------------------------------
// helpers
// ---------------------------------------------------------------------------
__device__ __forceinline__ uint32_t smem_u32(const void* p) {
    uint32_t a;
    asm("{ .reg .u64 t; cvta.to.shared.u64 t, %1; cvt.u32.u64 %0, t; }"
        : "=r"(a) : "l"(p));
    return a;
}
__device__ __forceinline__ void cp16(const void* dst, const void* src, bool full) {
    uint32_t d = smem_u32(dst);
    int sz = full ? 16 : 0;
    asm volatile("cp.async.cg.shared.global [%0], [%1], 16, %2;"
                 :: "r"(d), "l"(src), "r"(sz) : "memory");
}
#define CP_COMMIT() asm volatile("cp.async.commit_group;" ::: "memory")
#define CP_WAIT1()  asm volatile("cp.async.wait_group 1;" ::: "memory")
#define CP_WAIT0()  asm volatile("cp.async.wait_group 0;" ::: "memory")

__device__ __forceinline__ void ldsm4(uint32_t r[4], uint32_t addr) {
    asm volatile("ldmatrix.sync.aligned.m8n8.x4.shared.b16 {%0,%1,%2,%3}, [%4];"
                 : "=r"(r[0]), "=r"(r[1]), "=r"(r[2]), "=r"(r[3]) : "r"(addr));
}
__device__ __forceinline__ void ldsm4t(uint32_t r[4], uint32_t addr) {
    asm volatile("ldmatrix.sync.aligned.m8n8.x4.trans.shared.b16 {%0,%1,%2,%3}, [%4];"
                 : "=r"(r[0]), "=r"(r[1]), "=r"(r[2]), "=r"(r[3]) : "r"(addr));
}
__device__ __forceinline__ void mma16(float c[4], const uint32_t a[4], const uint32_t b[2]) {
    asm volatile(
        "mma.sync.aligned.m16n8k16.row.col.f32.f16.f16.f32 "
        "{%0,%1,%2,%3}, {%4,%5,%6,%7}, {%8,%9}, {%0,%1,%2,%3};"
        : "+f"(c[0]), "+f"(c[1]), "+f"(c[2]), "+f"(c[3])
        : "r"(a[0]), "r"(a[1]), "r"(a[2]), "r"(a[3]), "r"(b[0]), "r"(b[1]));
}

__device__ __forceinline__ uint4 pack8_f16(const float* __restrict__ s, int i) {
    const float4* s4 = (const float4*)s;
    float4 a = s4[2 * i], b = s4[2 * i + 1];
    __half2 h0 = __floats2half2_rn(a.x, a.y);
    __half2 h1 = __floats2half2_rn(a.z, a.w);
    __half2 h2 = __floats2half2_rn(b.x, b.y);
    __half2 h3 = __floats2half2_rn(b.z, b.w);
    uint4 o;
    o.x = *(uint32_t*)&h0; o.y = *(uint32_t*)&h1;
    o.z = *(uint32_t*)&h2; o.w = *(uint32_t*)&h3;
    return o;
}

// ---------------------------------------------------------------------------
// Kernel 0a/0b: f32 -> fp16 bulk converts (destinations are device globals,
// referenced in device code only — host cannot pass __device__ symbols)
// ---------------------------------------------------------------------------
__global__ void meg_convert(const float* __restrict__ s, int n8) {
    int i = blockIdx.x * blockDim.x + threadIdx.x;
    if (i >= n8) return;
    ((uint4*)g_megh)[i] = pack8_f16(s, i);
}
__global__ void heads_convert(const float* __restrict__ s, int n8) {
    int i = blockIdx.x * blockDim.x + threadIdx.x;
    if (i >= n8) return;
    ((uint4*)g_headsh)[i] = pack8_f16(s, i);
}

// ---------------------------------------------------------------------------
// Kernel 1: Fourier embedding (stores fp16)
// ---------------------------------------------------------------------------
__global__ void emb_kernel(const float* __restrict__ pos, int BC) {
    int row = blockIdx.x;
    if (row >= BC) return;
    int j = threadIdx.x;                    // 0..143
    float px = pos[2 * row]     + 0.2f;
    float py = pos[2 * row + 1] + 0.2f;
    const float w = 6.283185307179586f / 1.4f;
    int fi = j / NFREQ;
    int fj = j - fi * NFREQ;
    float loc = px * (w * (float)fi) + py * (w * (float)fj);
    float s, c;
    sincosf(loc, &s, &c);
    size_t base = (size_t)row * POS_DIM;
    g_embh[base + j]       = __float2half_rn(c);
    g_embh[base + 144 + j] = __float2half_rn(s);
}

// ---------------------------------------------------------------------------
// Kernel 2: scores[b,o,c] = sum_d heads[sid[b],o,d] * emb[b,c,d]
// fp16 m16n8k16, f32 accum, all-ldmatrix. Warp tile 32(o) x 32(c).
// 3-stage cp.async pipeline, 1 sync/chunk.
// ---------------------------------------------------------------------------
__global__ __launch_bounds__(256, 3)
void scores_mma(const int* __restrict__ sid, int B_, int C, int O) {
    extern __shared__ __half sh[];
    __half* As = sh;                    // [3][64][APH]
    __half* Es = sh + 3 * BM * APH;     // [3][128][APH]

    int tid = threadIdx.x, wid = tid >> 5, lane = tid & 31;
    int g = lane >> 2, tig = lane & 3;
    int b = blockIdx.z, o0 = blockIdx.y * BM, c0 = blockIdx.x * BN;
    int mi = (wid >> 2) * 32, ni = (wid & 3) * 32;

    int a_loff = (lane & 15) * APH + 8 * (lane >> 4);
    int e_loff = ((lane & 7) + 8 * (lane >> 4)) * APH + 8 * ((lane >> 3) & 1);

    const __half* hb = g_headsh + (size_t)sid[b] * O * POS_DIM;
    const __half* eb = g_embh   + (size_t)b * C * POS_DIM;

    float acc[2][4][4] = {};
    const int nch = POS_DIM / BK;   // 9

    auto load = [&](int j, int buf) {
        int k0 = j * BK;
        __half* A = As + buf * BM * APH;
        __half* E = Es + buf * BN * APH;
        {   // A: 64 rows x 32 halves = 256 cp16
            int m = tid >> 2, k8 = (tid & 3) * 8;
            int go = o0 + m;
            cp16(A + m * APH + k8,
                 hb + (size_t)(go < O ? go : 0) * POS_DIM + k0 + k8, go < O);
        }
        #pragma unroll
        for (int r = 0; r < 2; r++) {   // E: 128 rows x 32 halves = 512 cp16
            int idx = tid + r * 256;
            int m = idx >> 2, k8 = (idx & 3) * 8;
            int gc = c0 + m;
            cp16(E + m * APH + k8,
                 eb + (size_t)(gc < C ? gc : 0) * POS_DIM + k0 + k8, gc < C);
        }
        CP_COMMIT();
    };

    load(0, 0);
    if (nch > 1) load(1, 1);
    for (int j = 0; j < nch; j++) {
        int buf = j % 3;
        if (j + 1 < nch) CP_WAIT1(); else CP_WAIT0();
        __syncthreads();
        if (j + 2 < nch) load(j + 2, (j + 2) % 3);

        uint32_t Au = smem_u32(As + buf * BM * APH);
        uint32_t Eu = smem_u32(Es + buf * BN * APH);
        #pragma unroll
        for (int kk = 0; kk < BK; kk += 16) {
            uint32_t a[2][4], e[2][4];
            #pragma unroll
            for (int mt = 0; mt < 2; mt++)
                ldsm4(a[mt], Au + 2u * ((mi + mt * 16) * APH + kk + a_loff));
            #pragma unroll
            for (int nt = 0; nt < 2; nt++)
                ldsm4(e[nt], Eu + 2u * ((ni + nt * 16) * APH + kk + e_loff));
            #pragma unroll
            for (int mt = 0; mt < 2; mt++)
                #pragma unroll
                for (int nt = 0; nt < 2; nt++) {
                    mma16(acc[mt][2 * nt + 0], a[mt], &e[nt][0]);
                    mma16(acc[mt][2 * nt + 1], a[mt], &e[nt][2]);
                }
        }
    }

    float* outb = g_sc + (size_t)b * O * CP;
    #pragma unroll
    for (int mt = 0; mt < 2; mt++) {
        int r0 = o0 + mi + mt * 16 + g;
        int r1 = r0 + 8;
        #pragma unroll
        for (int nt = 0; nt < 4; nt++) {
            int gc = c0 + ni + nt * 8 + tig * 2;
            if (gc < CP) {
                if (r0 < O)
                    *(float2*)(outb + (size_t)r0 * CP + gc) =
                        make_float2(acc[mt][nt][0], acc[mt][nt][1]);
                if (r1 < O)
                    *(float2*)(outb + (size_t)r1 * CP + gc) =
                        make_float2(acc[mt][nt][2], acc[mt][nt][3]);
            }
        }
    }
}

// ---------------------------------------------------------------------------
// Kernel 3: masked softmax over C (f32 in), writes fp16 weights, zero pad.
// ---------------------------------------------------------------------------
__global__ void softmax_kernel(const float* __restrict__ pos,
                               int B_, int C, int O, int rows) {
    int gwarp = (blockIdx.x * blockDim.x + threadIdx.x) >> 5;
    int lane  = threadIdx.x & 31;
    if (gwarp >= rows) return;
    int b = gwarp / O;
    const float* row = g_sc + (size_t)gwarp * CP;
    __half* wrow = g_w + (size_t)gwarp * CP;
    const float* pb = pos + (size_t)b * C * 2;

    float v[9];
    float mx = -INFINITY;
    #pragma unroll
    for (int i = 0; i < 9; i++) {
        int c = lane + i * 32;
        float val = -INFINITY;
        if (c < C) {
            val = row[c];
            float px = pb[2 * c], py = pb[2 * c + 1];
            if (px == -0.1f && py == -0.1f) val = -INFINITY;
        }
        v[i] = val;
        mx = fmaxf(mx, val);
    }
    #pragma unroll
    for (int s = 16; s > 0; s >>= 1)
        mx = fmaxf(mx, __shfl_xor_sync(0xffffffffu, mx, s));

    float sum = 0.f;
    #pragma unroll
    for (int i = 0; i < 9; i++) {
        float e = expf(v[i] - mx);
        v[i] = e;
        sum += (lane + i * 32 < C) ? e : 0.f;
    }
    #pragma unroll
    for (int s = 16; s > 0; s >>= 1)
        sum += __shfl_xor_sync(0xffffffffu, sum, s);
    float inv = 1.f / sum;

    #pragma unroll
    for (int i = 0; i < 9; i++) {
        int c = lane + i * 32;
        if (c < C)       wrow[c] = __float2half_rn(v[i] * inv);
        else if (c < CP) wrow[c] = __float2half_rn(0.f);
    }
}

// ---------------------------------------------------------------------------
// Kernel 4 (dominant): out[b,o,t] = sum_c W[b,o,c] * meg[b,c,t]
// fp16 m16n8k16, f32 accum. A = fp16 weights (ldmatrix); B = fp16 meg [c][t]
// via ldmatrix.trans — zero scalar LDS, zero cvt. 3-stage pipeline.
// ---------------------------------------------------------------------------
__global__ __launch_bounds__(256, 3)
void out_mma(float* __restrict__ out, int B_, int C, int T, int O) {
    extern __shared__ __half sh[];
    __half* As = sh;                    // [3][64][APH]
    __half* Bs = sh + 3 * BM * APH;     // [3][32][BPH]

    int tid = threadIdx.x, wid = tid >> 5, lane = tid & 31;
    int g = lane >> 2, tig = lane & 3;
    int b = blockIdx.z, o0 = blockIdx.y * BM, t0 = blockIdx.x * ON;
    int mi = (wid >> 2) * 32, ni = (wid & 3) * 32;

    int a_loff = (lane & 15) * APH + 8 * (lane >> 4);
    int b_loff = ((lane & 7) + 8 * ((lane >> 3) & 1)) * BPH + 8 * (lane >> 4);

    const __half* wb = g_w    + (size_t)b * O * CP;
    const __half* mb = g_megh + (size_t)b * C * T;

    float acc[2][4][4] = {};
    const int nch = CP / BK;   // 9

    auto load = [&](int j, int buf) {
        int k0 = j * BK;
        __half* A  = As + buf * BM * APH;
        __half* Bt = Bs + buf * BK * BPH;
        {   // A: 64 x 32 halves = 256 cp16
            int m = tid >> 2, k8 = (tid & 3) * 8;
            int go = o0 + m;
            cp16(A + m * APH + k8,
                 wb + (size_t)(go < O ? go : 0) * CP + k0 + k8, go < O);
        }
        #pragma unroll
        for (int r = 0; r < 2; r++) {   // B: 32 x 128 halves = 512 cp16
            int idx = tid + r * 256;
            int c = idx >> 4, t8 = (idx & 15) * 8;
            int gc = k0 + c;
            cp16(Bt + c * BPH + t8,
                 mb + (size_t)(gc < C ? gc : 0) * T + t0 + t8, gc < C);
        }
        CP_COMMIT();
    };

    load(0, 0);
    if (nch > 1) load(1, 1);
    for (int j = 0; j < nch; j++) {
        int buf = j % 3;
        if (j + 1 < nch) CP_WAIT1(); else CP_WAIT0();
        __syncthreads();
        if (j + 2 < nch) load(j + 2, (j + 2) % 3);

        uint32_t Au = smem_u32(As + buf * BM * APH);
        uint32_t Bu = smem_u32(Bs + buf * BK * BPH);
        #pragma unroll
        for (int kk = 0; kk < BK; kk += 16) {
            uint32_t a[2][4], bf[2][4];
            #pragma unroll
            for (int mt = 0; mt < 2; mt++)
                ldsm4(a[mt], Au + 2u * ((mi + mt * 16) * APH + kk + a_loff));
            #pragma unroll
            for (int nt = 0; nt < 2; nt++)
                ldsm4t(bf[nt], Bu + 2u * (kk * BPH + ni + nt * 16 + b_loff));
            #pragma unroll
            for (int mt = 0; mt < 2; mt++)
                #pragma unroll
                for (int nt = 0; nt < 2; nt++) {
                    mma16(acc[mt][2 * nt + 0], a[mt], &bf[nt][0]);
                    mma16(acc[mt][2 * nt + 1], a[mt], &bf[nt][2]);
                }
        }
    }

    #pragma unroll
    for (int mt = 0; mt < 2; mt++) {
        int r0 = o0 + mi + mt * 16 + g;
        int r1 = r0 + 8;
        #pragma unroll
        for (int nt = 0; nt < 4; nt++) {
            int col = t0 + ni + nt * 8 + tig * 2;
            if (r0 < O)
                *(float2*)(out + ((size_t)b * O + r0) * T + col) =
                    make_float2(acc[mt][nt][0], acc[mt][nt][1]);
            if (r1 < O)
                *(float2*)(out + ((size_t)b * O + r1) * T + col) =
                    make_float2(acc[mt][nt][2], acc[mt][nt][3]);
        }
    }
}

// ---------------------------------------------------------------------------
// Launch. Inputs: meg f32 [B,C,T], positions f32 [B,C,2], subject_ids i32 [B],
// heads f32 [S,O,288]. Output f32 [B,O,T].
// ---------------------------------------------------------------------------
extern "C" void kernel_launch(void* const* d_in, const int* in_sizes, int n_in,
                              void* d_out, int out_size) {
    const float* meg   = (const float*)d_in[0];
    const float* pos   = (const float*)d_in[1];
    const int*   sid   = (const int*)  d_in[2];
    const float* heads = (const float*)d_in[3];
    float* out = (float*)d_out;

    int B = in_sizes[2];
    int C = in_sizes[1] / (2 * B);
    int T = in_sizes[0] / (B * C);
    int O = out_size / (B * T);

    const int smem_sc  = 3 * (BM + BN) * APH * 2;            // 46080 B
    const int smem_out = 3 * (BM * APH + BK * BPH) * 2;      // 41472 B
    cudaFuncSetAttribute(scores_mma, cudaFuncAttributeMaxDynamicSharedMemorySize, smem_sc);
    cudaFuncSetAttribute(out_mma,    cudaFuncAttributeMaxDynamicSharedMemorySize, smem_out);

    // 0) bulk converts to fp16 (device-global destinations, DRAM-bound)
    int n8m = in_sizes[0] / 8;
    meg_convert<<<(n8m + 255) / 256, 256>>>(meg, n8m);
    int n8h = in_sizes[3] / 8;
    heads_convert<<<(n8h + 255) / 256, 256>>>(heads, n8h);

    // 1) Fourier embedding (fp16)
    emb_kernel<<<B * C, 144>>>(pos, B * C);

    // 2) scores = heads[sid] @ emb^T  (fp16 HMMA, f32 accum, f32 scores out)
    dim3 gs((C + BN - 1) / BN, (O + BM - 1) / BM, B);
    scores_mma<<<gs, 256, smem_sc>>>(sid, B, C, O);

    // 3) masked softmax -> fp16 weights (+ zero pad to CP)
    int rows = B * O;
    int nblk = (rows * 32 + 255) / 256;
    softmax_kernel<<<nblk, 256>>>(pos, B, C, O, rows);

    // 4) out = weights @ meg  (fp16 HMMA, all-ldmatrix, trans B)
    dim3 gd(T / ON, (O + BM - 1) / BM, B);
    out_mma<<<gd, 256, smem_out>>>(out, B, C, T, O);
}